// round 13
// baseline (speedup 1.0000x reference)
#include <cuda_runtime.h>
#include <cuda_bf16.h>
#include <cuda_fp16.h>
#include <cstdint>

#define B_  4
#define L_  2048
#define H_  512
#define NH  8
#define D_  64
#define KP  40
#define QKP 40
#define FPP 80     // byte pitch for e4m3 tiles (64B rows)
#define LOG2E 1.4426950408889634f

// ---------------- scratch (static device globals; no allocation) ----------------
__device__ __nv_bfloat16 g_Abf[3*B_*L_*H_];    // bf16 q_in|k_in|v_in
__device__ __nv_bfloat16 g_Wbf[3*H_*H_];       // bf16 Wq|Wk|Wv
__device__ uint8_t g_Qf8[B_*NH*L_*D_];         // e4m3, q*0.5*log2e
__device__ uint8_t g_Kf8[B_*NH*L_*D_];         // e4m3, k*0.25
__device__ uint8_t g_Wpf8[4096*D_];            // e4m3, wp*16; rows >= 4095 zero
__device__ float g_V[B_*NH*L_*D_];             // fp32 head layout
__device__ float g_RS0[B_*NH*L_];
__device__ float g_RS1[B_*NH*L_];
__device__ float g_SD[B_*NH*L_];

__device__ __forceinline__ float fast_exp2(float x) {
    float y; asm("ex2.approx.f32 %0, %1;" : "=f"(y) : "f"(x)); return y;
}
__device__ __forceinline__ float fast_rcp(float x) {
    float y; asm("rcp.approx.f32 %0, %1;" : "=f"(y) : "f"(x)); return y;
}
__device__ __forceinline__ void mma16816(float* c, const uint32_t* a,
                                         uint32_t b0, uint32_t b1) {
    asm volatile(
        "mma.sync.aligned.m16n8k16.row.col.f32.bf16.bf16.f32 "
        "{%0,%1,%2,%3}, {%4,%5,%6,%7}, {%8,%9}, {%0,%1,%2,%3};"
        : "+f"(c[0]), "+f"(c[1]), "+f"(c[2]), "+f"(c[3])
        : "r"(a[0]), "r"(a[1]), "r"(a[2]), "r"(a[3]), "r"(b0), "r"(b1));
}
__device__ __forceinline__ void mma_f8(float* c, const uint32_t* a,
                                       uint32_t b0, uint32_t b1) {
    asm volatile(
        "mma.sync.aligned.m16n8k32.row.col.f32.e4m3.e4m3.f32 "
        "{%0,%1,%2,%3}, {%4,%5,%6,%7}, {%8,%9}, {%0,%1,%2,%3};"
        : "+f"(c[0]), "+f"(c[1]), "+f"(c[2]), "+f"(c[3])
        : "r"(a[0]), "r"(a[1]), "r"(a[2]), "r"(a[3]), "r"(b0), "r"(b1));
}
__device__ __forceinline__ void ldsm_x4(uint32_t* r, uint32_t addr) {
    asm volatile("ldmatrix.sync.aligned.m8n8.x4.shared.b16 {%0,%1,%2,%3}, [%4];"
        : "=r"(r[0]), "=r"(r[1]), "=r"(r[2]), "=r"(r[3]) : "r"(addr));
}
__device__ __forceinline__ uint32_t smem_u32(const void* p) {
    uint32_t a;
    asm("{ .reg .u64 t; cvta.to.shared.u64 t, %1; cvt.u32.u64 %0, t; }" : "=r"(a) : "l"(p));
    return a;
}
__device__ __forceinline__ void cp16(uint32_t s, const void* g) {
    asm volatile("cp.async.cg.shared.global [%0], [%1], 16;" :: "r"(s), "l"(g));
}
#define CP_COMMIT() asm volatile("cp.async.commit_group;" ::: "memory")

__device__ __forceinline__ __nv_bfloat162 cvt2(float x, float y) {
    return __halves2bfloat162(__float2bfloat16(x), __float2bfloat16(y));
}
__device__ __forceinline__ uint16_t cvt_e4m3x2(float lo, float hi) {
    uint16_t r;
    asm("cvt.rn.satfinite.e4m3x2.f32 %0, %1, %2;" : "=h"(r) : "f"(hi), "f"(lo));
    return r;
}
__device__ __forceinline__ void exp2_acc_f16x2(uint32_t& hacc, float a, float b) {
    uint32_t p, e;
    asm("cvt.rn.f16x2.f32 %0, %1, %2;" : "=r"(p) : "f"(b), "f"(a));
    asm("ex2.approx.f16x2 %0, %1;" : "=r"(e) : "r"(p));
    asm("add.rn.f16x2 %0, %0, %1;" : "+r"(hacc) : "r"(e));
}

// ---------------- Kernel 0: convert inputs/weights/Wp ---------------------------
__global__ __launch_bounds__(256)
void convert_kernel(const float* __restrict__ q, const float* __restrict__ k,
                    const float* __restrict__ v,
                    const float* __restrict__ wq, const float* __restrict__ wk,
                    const float* __restrict__ wv, const float* __restrict__ wp)
{
    const int ACT4 = (B_*L_*H_)/4;
    const int WT4  = (H_*H_)/4;
    int i4 = blockIdx.x*256 + threadIdx.x;
    if (i4 < 3*ACT4) {
        int seg = i4 / ACT4, off = (i4 - seg*ACT4)*4;
        const float* s = seg == 0 ? q : (seg == 1 ? k : v);
        float4 val = *(const float4*)(s + off);
        __nv_bfloat162* d = (__nv_bfloat162*)(g_Abf + (size_t)seg*(B_*L_*H_) + off);
        d[0] = cvt2(val.x, val.y); d[1] = cvt2(val.z, val.w);
    } else if (i4 < 3*ACT4 + 3*WT4) {
        int j = i4 - 3*ACT4, seg = j / WT4, off = (j - seg*WT4)*4;
        const float* s = seg == 0 ? wq : (seg == 1 ? wk : wv);
        float4 val = *(const float4*)(s + off);
        __nv_bfloat162* d = (__nv_bfloat162*)(g_Wbf + seg*(H_*H_) + off);
        d[0] = cvt2(val.x, val.y); d[1] = cvt2(val.z, val.w);
    } else {
        int off = (i4 - 3*ACT4 - 3*WT4)*4;    // < 262144 elements
        int r = off >> 6;
        float4 val = make_float4(0.f, 0.f, 0.f, 0.f);
        if (r < 2*L_ - 1) val = *(const float4*)(wp + off);
        uint32_t lo = cvt_e4m3x2(val.x*16.f, val.y*16.f);
        uint32_t hi = cvt_e4m3x2(val.z*16.f, val.w*16.f);
        *(uint32_t*)(g_Wpf8 + off) = lo | (hi << 16);
    }
}

// ---------------- Kernel 1: QKV projections, 3-stage cp.async bf16 GEMM ---------
#define QKV_SMEM (6*128*QKP*2)

__global__ __launch_bounds__(256, 2)
void gemm_qkv_bf16(const float* __restrict__ bq, const float* __restrict__ bk,
                   const float* __restrict__ bv)
{
    extern __shared__ __nv_bfloat16 qsm[];
    int mode = blockIdx.z;
    const __nv_bfloat16* A = g_Abf + (size_t)mode*(B_*L_*H_);
    const __nv_bfloat16* W = g_Wbf + mode*(H_*H_);
    const float* bias = mode == 0 ? bq : (mode == 1 ? bk : bv);

    const int m0 = blockIdx.y * 128, n0 = blockIdx.x * 128;
    const int tid = threadIdx.x, lane = tid & 31, w = tid >> 5;
    const int wr = w >> 1, wc = w & 1, g = lane >> 2, qd = lane & 3;

    __nv_bfloat16* Abuf[3]; __nv_bfloat16* Wbuf[3];
    #pragma unroll
    for (int b = 0; b < 3; b++) {
        Abuf[b] = qsm + b*2*128*QKP;
        Wbuf[b] = Abuf[b] + 128*QKP;
    }

    auto cp_chunk = [&](int kc) {
        int b = kc % 3;
        uint32_t as = smem_u32(Abuf[b]);
        uint32_t ws = smem_u32(Wbuf[b]);
        const __nv_bfloat16* Ag = A + (size_t)m0 * H_ + kc*32;
        const __nv_bfloat16* Wg = W + (size_t)n0 * H_ + kc*32;
        #pragma unroll
        for (int t = tid; t < 512; t += 256) {
            int r = t >> 2, c = (t & 3) * 8;
            cp16(as + (r*QKP + c)*2, Ag + (size_t)r * H_ + c);
            cp16(ws + (r*QKP + c)*2, Wg + (size_t)r * H_ + c);
        }
        CP_COMMIT();
    };

    uint32_t qaA[3], wbaA[3];
    #pragma unroll
    for (int b = 0; b < 3; b++) {
        qaA[b]  = smem_u32(Abuf[b] + (wr*32 + (lane & 15))*QKP + ((lane >> 4) & 1)*8);
        wbaA[b] = smem_u32(Wbuf[b] + (wc*64 + ((lane >> 4) & 1)*8 + (lane & 7))*QKP
                           + ((lane >> 3) & 1)*8);
    }

    float acc[2][8][4] = {};

    cp_chunk(0);
    cp_chunk(1);

    for (int kc = 0; kc < 16; kc++) {
        if (kc < 15) asm volatile("cp.async.wait_group 1;" ::: "memory");
        else         asm volatile("cp.async.wait_group 0;" ::: "memory");
        __syncthreads();
        if (kc < 14) cp_chunk(kc + 2);

        int b = kc % 3;
        #pragma unroll
        for (int kk = 0; kk < 2; kk++) {
            uint32_t a0[4], a1[4];
            ldsm_x4(a0, qaA[b] + kk*32);
            ldsm_x4(a1, qaA[b] + 16*QKP*2 + kk*32);
            #pragma unroll
            for (int p = 0; p < 4; p++) {
                uint32_t bb[4];
                ldsm_x4(bb, wbaA[b] + p*(16*QKP*2) + kk*32);
                mma16816(acc[0][2*p+0], a0, bb[0], bb[1]);
                mma16816(acc[0][2*p+1], a0, bb[2], bb[3]);
                mma16816(acc[1][2*p+0], a1, bb[0], bb[1]);
                mma16816(acc[1][2*p+1], a1, bb[2], bb[3]);
            }
        }
    }

    const float qsA = 0.5f * LOG2E;   // q scale for e4m3 (0.125*log2e*4)
    #pragma unroll
    for (int mf = 0; mf < 2; mf++) {
        int rg = m0 + wr*32 + mf*16 + g;
        int b = rg >> 11, l = rg & (L_ - 1);
        #pragma unroll
        for (int nf = 0; nf < 8; nf++) {
            int n = n0 + wc*64 + nf*8 + qd*2;
            int h = n >> 6, d = n & 63;
            float b0 = bias[n], b1 = bias[n+1];
            float v00 = acc[mf][nf][0] + b0, v01 = acc[mf][nf][1] + b1;
            float v10 = acc[mf][nf][2] + b0, v11 = acc[mf][nf][3] + b1;
            size_t o0 = ((size_t)(b*NH + h) * L_ + l) * D_ + d;
            size_t o1 = o0 + 8*D_;
            if (mode == 0) {
                *(uint16_t*)(g_Qf8 + o0) = cvt_e4m3x2(v00*qsA, v01*qsA);
                *(uint16_t*)(g_Qf8 + o1) = cvt_e4m3x2(v10*qsA, v11*qsA);
            } else if (mode == 1) {
                *(uint16_t*)(g_Kf8 + o0) = cvt_e4m3x2(v00*0.25f, v01*0.25f);
                *(uint16_t*)(g_Kf8 + o1) = cvt_e4m3x2(v10*0.25f, v11*0.25f);
            } else {
                *(float2*)(g_V + o0) = make_float2(v00, v01);
                *(float2*)(g_V + o1) = make_float2(v10, v11);
            }
        }
    }
}

// ---------------- Kernel 2: e4m3 MMA score pass ---------------------------------
#define PSP 520
#define AOFF_KS0 10240
#define AOFF_KS1 20480
#define AOFF_WS0 30720
#define AOFF_WS1 40960
#define AOFF_PS  51200
#define AOFF_WB  184320
#define AOFF_SD  185344
#define AOFF_RED 185856
#define ATT_SMEM 187904

__global__ __launch_bounds__(512, 1)
void attn_mma_kernel(const float* __restrict__ Wpb)
{
    extern __shared__ char smc[];
    __nv_bfloat16* Psm = (__nv_bfloat16*)(smc + AOFF_PS);
    float* wbn   = (float*)(smc + AOFF_WB);
    float* sdArr = (float*)(smc + AOFF_SD);
    float* red   = (float*)(smc + AOFF_RED);

    const int tid = threadIdx.x;
    const int lane = tid & 31, w = tid >> 5;
    const int wr = w >> 2, wc = w & 3;
    const int g = lane >> 2, qd = lane & 3;
    const int bh = blockIdx.y, it = blockIdx.x;
    const int half = blockIdx.z;
    const int js = half * 8;
    const int i0 = it * 128;
    const int rbase0 = 1920 - 128*it;

    const uint32_t qs_s = smem_u32(smc);
    const uint32_t ks_s[2] = { qs_s + AOFF_KS0, qs_s + AOFF_KS1 };
    const uint32_t ws_s[2] = { qs_s + AOFF_WS0, qs_s + AOFF_WS1 };

    // 128-row x 64-byte e4m3 tile, pitch FPP; one cp16 per thread
    auto cp_tile = [&](uint32_t sbase, const uint8_t* gsrc) {
        int r = tid >> 2, c = (tid & 3) * 16;
        cp16(sbase + r*FPP + c, gsrc + r*64 + c);
    };

    // ---- prolog (all loads async, one group)
    cp_tile(qs_s,   g_Qf8 + ((size_t)bh * L_ + i0) * D_);
    cp_tile(ks_s[0], g_Kf8 + ((size_t)bh * L_ + js*128) * D_);
    cp_tile(ws_s[1], g_Wpf8 + (size_t)(rbase0 + js*128) * D_);
    cp_tile(ws_s[0], g_Wpf8 + (size_t)(rbase0 + (js+1)*128) * D_);
    CP_COMMIT();
    if (tid < 128) {
        int ia = rbase0 + js*128 + tid;
        int ib = rbase0 + (js+1)*128 + tid;
        wbn[128 + tid] = (ia < 2*L_ - 1) ? Wpb[ia] * LOG2E : 0.f;
        wbn[tid]       = (ib < 2*L_ - 1) ? Wpb[ib] * LOG2E : 0.f;
    }
    asm volatile("cp.async.wait_group 0;" ::: "memory");
    __syncthreads();

    // Q fragments cached for whole kernel
    uint32_t qf[2][2][4];
    {
        uint32_t qa0 = qs_s + (wr*32 + (lane & 15))*FPP + ((lane >> 4) & 1)*16;
        uint32_t qa1 = qa0 + 16*FPP;
        #pragma unroll
        for (int kk = 0; kk < 2; kk++) {
            ldsm_x4(qf[kk][0], qa0 + kk*32);
            ldsm_x4(qf[kk][1], qa1 + kk*32);
        }
    }

    const uint32_t boff = (((lane >> 4) & 1)*8 + (lane & 7))*FPP + ((lane >> 3) & 1)*16;
    const uint32_t bline = wc*32*FPP;

    float accP[2][2][4];
    float accS[2][4][4];
    float rs[4] = {0.f, 0.f, 0.f, 0.f};

    auto pblock_half = [&](uint32_t ws_base, int h) {
        #pragma unroll
        for (int mf = 0; mf < 2; mf++)
            #pragma unroll
            for (int nf = 0; nf < 2; nf++)
                #pragma unroll
                for (int k = 0; k < 4; k++) accP[mf][nf][k] = 0.f;
        const uint32_t ba = ws_base + bline + boff + h*(16*FPP);
        #pragma unroll
        for (int kk = 0; kk < 2; kk++) {
            uint32_t bb[4];
            ldsm_x4(bb, ba + kk*32);
            mma_f8(accP[0][0], qf[kk][0], bb[0], bb[1]);
            mma_f8(accP[0][1], qf[kk][0], bb[2], bb[3]);
            mma_f8(accP[1][0], qf[kk][1], bb[0], bb[1]);
            mma_f8(accP[1][1], qf[kk][1], bb[2], bb[3]);
        }
    };
    auto store_half = [&](const float* wb, int slot, int h) {
        int pb = slot * 128;
        const float ps = 0.015625f;   // 1/64: undo q*4 and wp*16 scaling
        #pragma unroll
        for (int mf = 0; mf < 2; mf++) {
            int r0 = wr*32 + mf*16 + g, r1 = r0 + 8;
            #pragma unroll
            for (int nf = 0; nf < 2; nf++) {
                int c = wc*32 + (h*2 + nf)*8 + qd*2;
                float b0 = wb[c], b1 = wb[c+1];
                __nv_bfloat162 v0 = cvt2(accP[mf][nf][0]*ps + b0, accP[mf][nf][1]*ps + b1);
                __nv_bfloat162 v1 = cvt2(accP[mf][nf][2]*ps + b0, accP[mf][nf][3]*ps + b1);
                *(__nv_bfloat162*)&Psm[r0*PSP + pb + c] = v0;
                *(__nv_bfloat162*)&Psm[r1*PSP + pb + c] = v1;
                if (slot == 0) {
                    *(__nv_bfloat162*)&Psm[r0*PSP + 384 + c] = v0;
                    *(__nv_bfloat162*)&Psm[r1*PSP + 384 + c] = v1;
                }
            }
        }
    };
    auto smma = [&](uint32_t ks_base) {
        #pragma unroll
        for (int mf = 0; mf < 2; mf++)
            #pragma unroll
            for (int nf = 0; nf < 4; nf++)
                #pragma unroll
                for (int k = 0; k < 4; k++) accS[mf][nf][k] = 0.f;
        const uint32_t kb0a = ks_base + bline + boff;
        const uint32_t kb1a = kb0a + 16*FPP;
        #pragma unroll
        for (int kk = 0; kk < 2; kk++) {
            uint32_t b0v[4], b1v[4];
            ldsm_x4(b0v, kb0a + kk*32);
            ldsm_x4(b1v, kb1a + kk*32);
            mma_f8(accS[0][0], qf[kk][0], b0v[0], b0v[1]);
            mma_f8(accS[0][1], qf[kk][0], b0v[2], b0v[3]);
            mma_f8(accS[0][2], qf[kk][0], b1v[0], b1v[1]);
            mma_f8(accS[0][3], qf[kk][0], b1v[2], b1v[3]);
            mma_f8(accS[1][0], qf[kk][1], b0v[0], b0v[1]);
            mma_f8(accS[1][1], qf[kk][1], b0v[2], b0v[3]);
            mma_f8(accS[1][2], qf[kk][1], b1v[0], b1v[1]);
            mma_f8(accS[1][3], qf[kk][1], b1v[2], b1v[3]);
        }
    };
    auto epilogue = [&](int psig, bool dt) {
        int off = psig*128 + 127;
        uint32_t hacc[4] = {0u, 0u, 0u, 0u};
        #pragma unroll
        for (int mf = 0; mf < 2; mf++) {
            int r0 = wr*32 + mf*16 + g, r1 = r0 + 8;
            const __nv_bfloat16* base0 = Psm + r0*PSP + off - r0;
            const __nv_bfloat16* base1 = Psm + r1*PSP + off - r1;
            #pragma unroll
            for (int nf = 0; nf < 4; nf++) {
                int j = wc*32 + nf*8 + qd*2;
                float t00 = accS[mf][nf][0] + __bfloat162float(base0[j]);
                float t01 = accS[mf][nf][1] + __bfloat162float(base0[j+1]);
                float t10 = accS[mf][nf][2] + __bfloat162float(base1[j]);
                float t11 = accS[mf][nf][3] + __bfloat162float(base1[j+1]);
                exp2_acc_f16x2(hacc[mf*2+0], t00, t01);
                exp2_acc_f16x2(hacc[mf*2+1], t10, t11);
                if (dt) {
                    if (j == r0)          sdArr[r0] = t00;
                    else if (j + 1 == r0) sdArr[r0] = t01;
                    if (j == r1)          sdArr[r1] = t10;
                    else if (j + 1 == r1) sdArr[r1] = t11;
                }
            }
        }
        #pragma unroll
        for (int k = 0; k < 4; k++) {
            __half2 hv = *reinterpret_cast<__half2*>(&hacc[k]);
            rs[k] += __low2float(hv) + __high2float(hv);
        }
    };

    int sigma = (((rbase0 >> 7) + js)) % 3;
    pblock_half(ws_s[1], 0); store_half(wbn + 128, sigma, 0);
    pblock_half(ws_s[1], 1); store_half(wbn + 128, sigma, 1);

    int psig = sigma;

    for (int jt = js; jt < js + 8; jt++) {
        int t = jt - js;
        int cur = t & 1, nxt = cur ^ 1;
        int s_w = sigma + 1; if (s_w == 3) s_w = 0;

        asm volatile("cp.async.wait_group 0;" ::: "memory");
        __syncthreads();

        if (t < 7) {
            if (tid < 128) {
                int idx = rbase0 + (jt+2)*128 + tid;
                wbn[nxt*128 + tid] = (idx < 2*L_ - 1) ? Wpb[idx] * LOG2E : 0.f;
            }
            cp_tile(ks_s[nxt], g_Kf8 + ((size_t)bh * L_ + (jt+1)*128) * D_);
            cp_tile(ws_s[nxt], g_Wpf8 + (size_t)(rbase0 + (jt+2)*128) * D_);
            CP_COMMIT();
        }

        pblock_half(ws_s[cur], 0); store_half(wbn + cur*128, s_w, 0);
        pblock_half(ws_s[cur], 1); store_half(wbn + cur*128, s_w, 1);
        if (t > 0) epilogue(psig, (jt-1) == it);
        smma(ks_s[cur]);

        psig = sigma; sigma = s_w;
    }

    __syncthreads();
    epilogue(psig, (js + 7) == it);

    #pragma unroll
    for (int k = 0; k < 4; k++) {
        rs[k] += __shfl_xor_sync(0xffffffffu, rs[k], 1);
        rs[k] += __shfl_xor_sync(0xffffffffu, rs[k], 2);
    }
    if (qd == 0) {
        int base = wc*128 + wr*32 + g;
        red[base]      = rs[0];
        red[base + 8]  = rs[1];
        red[base + 16] = rs[2];
        red[base + 24] = rs[3];
    }
    __syncthreads();
    if (tid < 128) {
        float r = red[tid] + red[128 + tid] + red[256 + tid] + red[384 + tid];
        size_t o = (size_t)bh * L_ + i0 + tid;
        if (half) g_RS1[o] = r; else g_RS0[o] = r;
        if ((it >> 3) == half) g_SD[o] = sdArr[tid];
    }
}

// ---------------- Kernel 3: O projection, smem diag table, fused diag*V ---------
__global__ __launch_bounds__(256, 2)
void gemm_out_bf16(const float* __restrict__ Wo, const float* __restrict__ bo,
                   float* __restrict__ out)
{
    __shared__ __nv_bfloat16 Ab[2][128*KP];
    __shared__ __nv_bfloat16 Wb[2][128*KP];
    __shared__ float dgs[NH*128];

    const int m0 = blockIdx.y * 128, n0 = blockIdx.x * 128;
    const int tid = threadIdx.x, lane = tid & 31, w = tid >> 5;
    const int wr = w >> 1, wc = w & 1, g = lane >> 2, qd = lane & 3;
    const int rr = tid >> 3;
    const int c4 = (tid & 7) * 4;

    const int bq = m0 >> 11, l0 = m0 & (L_ - 1);

    // precompute all diag values for this m-tile (off the critical path)
    for (int t = tid; t < NH*128; t += 256) {
        int h = t >> 7, r = t & 127;
        size_t row = (size_t)(bq*NH + h) * L_ + l0 + r;
        dgs[t] = fast_exp2(g_SD[row]) * fast_rcp(g_RS0[row] + g_RS1[row]);
    }
    __syncthreads();

    float4 ra[4], rw[4];
    auto ldg_chunk = [&](int kc) {
        int h = kc >> 1;
        const float* Ag = g_V + ((size_t)(bq*NH + h) * L_ + l0) * D_ + (kc & 1)*32;
        const float* Wg = Wo + (size_t)n0 * H_ + kc*32;
        #pragma unroll
        for (int i = 0; i < 4; i++) {
            int r = i*32 + rr;
            ra[i] = *(const float4*)&Ag[(size_t)r * D_ + c4];
            rw[i] = *(const float4*)&Wg[(size_t)r * H_ + c4];
        }
    };
    auto sts_chunk = [&](int buf, int kc) {
        const float* dg = dgs + (kc >> 1)*128;
        #pragma unroll
        for (int i = 0; i < 4; i++) {
            int r = i*32 + rr;
            float d = dg[r];
            __nv_bfloat162* pa = (__nv_bfloat162*)(Ab[buf] + r*KP + c4);
            pa[0] = cvt2(ra[i].x*d, ra[i].y*d);
            pa[1] = cvt2(ra[i].z*d, ra[i].w*d);
            __nv_bfloat162* pw = (__nv_bfloat162*)(Wb[buf] + r*KP + c4);
            pw[0] = cvt2(rw[i].x, rw[i].y);
            pw[1] = cvt2(rw[i].z, rw[i].w);
        }
    };

    uint32_t qaA[2], wbaA[2];
    #pragma unroll
    for (int b = 0; b < 2; b++) {
        qaA[b]  = smem_u32(Ab[b] + (wr*32 + (lane & 15))*KP + ((lane >> 4) & 1)*8);
        wbaA[b] = smem_u32(Wb[b] + (wc*64 + ((lane >> 4) & 1)*8 + (lane & 7))*KP
                           + ((lane >> 3) & 1)*8);
    }

    float acc[2][8][4] = {};

    ldg_chunk(0);
    sts_chunk(0, 0);
    ldg_chunk(1);

    for (int kc = 0; kc < 16; kc++) {
        int cur = kc & 1;
        __syncthreads();
        #pragma unroll
        for (int kk = 0; kk < 2; kk++) {
            uint32_t a0[4], a1[4];
            ldsm_x4(a0, qaA[cur] + kk*32);
            ldsm_x4(a1, qaA[cur] + 16*KP*2 + kk*32);
            #pragma unroll
            for (int p = 0; p < 4; p++) {
                uint32_t bb[4];
                ldsm_x4(bb, wbaA[cur] + p*(16*KP*2) + kk*32);
                mma16816(acc[0][2*p+0], a0, bb[0], bb[1]);
                mma16816(acc[0][2*p+1], a0, bb[2], bb[3]);
                mma16816(acc[1][2*p+0], a1, bb[0], bb[1]);
                mma16816(acc[1][2*p+1], a1, bb[2], bb[3]);
            }
        }
        if (kc < 15) {
            sts_chunk(cur ^ 1, kc + 1);
            if (kc < 14) ldg_chunk(kc + 2);
        }
    }

    #pragma unroll
    for (int mf = 0; mf < 2; mf++) {
        int rg = m0 + wr*32 + mf*16 + g;
        #pragma unroll
        for (int nf = 0; nf < 8; nf++) {
            int n = n0 + wc*64 + nf*8 + qd*2;
            float b0 = bo[n], b1 = bo[n+1];
            *(float2*)(out + (size_t)rg * H_ + n) =
                make_float2(acc[mf][nf][0] + b0, acc[mf][nf][1] + b1);
            *(float2*)(out + (size_t)(rg + 8) * H_ + n) =
                make_float2(acc[mf][nf][2] + b0, acc[mf][nf][3] + b1);
        }
    }
}

// ---------------- launch --------------------------------------------------------
extern "C" void kernel_launch(void* const* d_in, const int* in_sizes, int n_in,
                              void* d_out, int out_size)
{
    const float* q_in = (const float*)d_in[0];
    const float* k_in = (const float*)d_in[1];
    const float* v_in = (const float*)d_in[2];
    const float* Wq_w = (const float*)d_in[3];
    const float* Wq_b = (const float*)d_in[4];
    const float* Wk_w = (const float*)d_in[5];
    const float* Wk_b = (const float*)d_in[6];
    const float* Wv_w = (const float*)d_in[7];
    const float* Wv_b = (const float*)d_in[8];
    const float* Wo_w = (const float*)d_in[9];
    const float* Wo_b = (const float*)d_in[10];
    const float* Wp_w = (const float*)d_in[11];
    const float* Wp_b = (const float*)d_in[12];

    cudaFuncSetAttribute(attn_mma_kernel,
                         cudaFuncAttributeMaxDynamicSharedMemorySize, ATT_SMEM);
    cudaFuncSetAttribute(gemm_qkv_bf16,
                         cudaFuncAttributeMaxDynamicSharedMemorySize, QKV_SMEM);

    convert_kernel<<<13312, 256>>>(q_in, k_in, v_in, Wq_w, Wk_w, Wv_w, Wp_w);

    gemm_qkv_bf16<<<dim3(H_/128, (B_*L_)/128, 3), 256, QKV_SMEM>>>(Wq_b, Wk_b, Wv_b);

    attn_mma_kernel<<<dim3(L_/128, B_*NH, 2), 512, ATT_SMEM>>>(Wp_b);

    gemm_out_bf16<<<dim3(H_/128, (B_*L_)/128), 256>>>(Wo_w, Wo_b, (float*)d_out);
}

// round 15
// speedup vs baseline: 1.0447x; 1.0447x over previous
#include <cuda_runtime.h>
#include <cuda_bf16.h>
#include <cuda_fp16.h>
#include <cstdint>

#define B_  4
#define L_  2048
#define H_  512
#define NH  8
#define D_  64
#define KP  40
#define QKP 40
#define FPP 80     // byte pitch for e4m3 tiles (64B rows); multiple of 16 for ldmatrix
#define LOG2E 1.4426950408889634f

// ---------------- scratch (static device globals; no allocation) ----------------
__device__ __nv_bfloat16 g_Abf[3*B_*L_*H_];    // bf16 q_in|k_in|v_in
__device__ __nv_bfloat16 g_Wbf[3*H_*H_];       // bf16 Wq|Wk|Wv
__device__ uint8_t g_Qf8[B_*NH*L_*D_];         // e4m3, q*0.5*log2e
__device__ uint8_t g_Kf8[B_*NH*L_*D_];         // e4m3, k*0.25
__device__ uint8_t g_Wpf8[4096*D_];            // e4m3, wp*16; rows >= 4095 zero
__device__ float g_V[B_*NH*L_*D_];             // fp32 head layout
__device__ float g_RS0[B_*NH*L_];
__device__ float g_RS1[B_*NH*L_];
__device__ float g_SD[B_*NH*L_];

__device__ __forceinline__ float fast_exp2(float x) {
    float y; asm("ex2.approx.f32 %0, %1;" : "=f"(y) : "f"(x)); return y;
}
__device__ __forceinline__ float fast_rcp(float x) {
    float y; asm("rcp.approx.f32 %0, %1;" : "=f"(y) : "f"(x)); return y;
}
__device__ __forceinline__ void mma16816(float* c, const uint32_t* a,
                                         uint32_t b0, uint32_t b1) {
    asm volatile(
        "mma.sync.aligned.m16n8k16.row.col.f32.bf16.bf16.f32 "
        "{%0,%1,%2,%3}, {%4,%5,%6,%7}, {%8,%9}, {%0,%1,%2,%3};"
        : "+f"(c[0]), "+f"(c[1]), "+f"(c[2]), "+f"(c[3])
        : "r"(a[0]), "r"(a[1]), "r"(a[2]), "r"(a[3]), "r"(b0), "r"(b1));
}
__device__ __forceinline__ void mma_f8(float* c, const uint32_t* a,
                                       uint32_t b0, uint32_t b1) {
    asm volatile(
        "mma.sync.aligned.m16n8k32.row.col.f32.e4m3.e4m3.f32 "
        "{%0,%1,%2,%3}, {%4,%5,%6,%7}, {%8,%9}, {%0,%1,%2,%3};"
        : "+f"(c[0]), "+f"(c[1]), "+f"(c[2]), "+f"(c[3])
        : "r"(a[0]), "r"(a[1]), "r"(a[2]), "r"(a[3]), "r"(b0), "r"(b1));
}
__device__ __forceinline__ void mma_f8_z(float* c, const uint32_t* a,
                                         uint32_t b0, uint32_t b1) {
    asm volatile(
        "mma.sync.aligned.m16n8k32.row.col.f32.e4m3.e4m3.f32 "
        "{%0,%1,%2,%3}, {%4,%5,%6,%7}, {%8,%9}, {%10,%10,%10,%10};"
        : "=f"(c[0]), "=f"(c[1]), "=f"(c[2]), "=f"(c[3])
        : "r"(a[0]), "r"(a[1]), "r"(a[2]), "r"(a[3]), "r"(b0), "r"(b1), "f"(0.f));
}
__device__ __forceinline__ void ldsm_x4(uint32_t* r, uint32_t addr) {
    asm volatile("ldmatrix.sync.aligned.m8n8.x4.shared.b16 {%0,%1,%2,%3}, [%4];"
        : "=r"(r[0]), "=r"(r[1]), "=r"(r[2]), "=r"(r[3]) : "r"(addr));
}
__device__ __forceinline__ uint32_t smem_u32(const void* p) {
    uint32_t a;
    asm("{ .reg .u64 t; cvta.to.shared.u64 t, %1; cvt.u32.u64 %0, t; }" : "=r"(a) : "l"(p));
    return a;
}
__device__ __forceinline__ void cp16(uint32_t s, const void* g) {
    asm volatile("cp.async.cg.shared.global [%0], [%1], 16;" :: "r"(s), "l"(g));
}
#define CP_COMMIT() asm volatile("cp.async.commit_group;" ::: "memory")

__device__ __forceinline__ __nv_bfloat162 cvt2(float x, float y) {
    return __halves2bfloat162(__float2bfloat16(x), __float2bfloat16(y));
}
__device__ __forceinline__ uint16_t cvt_e4m3x2(float lo, float hi) {
    uint16_t r;
    asm("cvt.rn.satfinite.e4m3x2.f32 %0, %1, %2;" : "=h"(r) : "f"(hi), "f"(lo));
    return r;
}
__device__ __forceinline__ void exp2_acc_f16x2(uint32_t& hacc, float a, float b) {
    uint32_t p, e;
    asm("cvt.rn.f16x2.f32 %0, %1, %2;" : "=r"(p) : "f"(b), "f"(a));
    asm("ex2.approx.f16x2 %0, %1;" : "=r"(e) : "r"(p));
    asm("add.rn.f16x2 %0, %0, %1;" : "+r"(hacc) : "r"(e));
}

// ---------------- Kernel 0: convert inputs/weights/Wp ---------------------------
__global__ __launch_bounds__(256)
void convert_kernel(const float* __restrict__ q, const float* __restrict__ k,
                    const float* __restrict__ v,
                    const float* __restrict__ wq, const float* __restrict__ wk,
                    const float* __restrict__ wv, const float* __restrict__ wp)
{
    const int ACT4 = (B_*L_*H_)/4;
    const int WT4  = (H_*H_)/4;
    int i4 = blockIdx.x*256 + threadIdx.x;
    if (i4 < 3*ACT4) {
        int seg = i4 / ACT4, off = (i4 - seg*ACT4)*4;
        const float* s = seg == 0 ? q : (seg == 1 ? k : v);
        float4 val = *(const float4*)(s + off);
        __nv_bfloat162* d = (__nv_bfloat162*)(g_Abf + (size_t)seg*(B_*L_*H_) + off);
        d[0] = cvt2(val.x, val.y); d[1] = cvt2(val.z, val.w);
    } else if (i4 < 3*ACT4 + 3*WT4) {
        int j = i4 - 3*ACT4, seg = j / WT4, off = (j - seg*WT4)*4;
        const float* s = seg == 0 ? wq : (seg == 1 ? wk : wv);
        float4 val = *(const float4*)(s + off);
        __nv_bfloat162* d = (__nv_bfloat162*)(g_Wbf + seg*(H_*H_) + off);
        d[0] = cvt2(val.x, val.y); d[1] = cvt2(val.z, val.w);
    } else {
        int off = (i4 - 3*ACT4 - 3*WT4)*4;
        int r = off >> 6;
        float4 val = make_float4(0.f, 0.f, 0.f, 0.f);
        if (r < 2*L_ - 1) val = *(const float4*)(wp + off);
        uint32_t lo = cvt_e4m3x2(val.x*16.f, val.y*16.f);
        uint32_t hi = cvt_e4m3x2(val.z*16.f, val.w*16.f);
        *(uint32_t*)(g_Wpf8 + off) = lo | (hi << 16);
    }
}

// ---------------- Kernel 1: QKV projections, 3-stage cp.async bf16 GEMM ---------
#define QKV_SMEM (6*128*QKP*2)

__global__ __launch_bounds__(256, 2)
void gemm_qkv_bf16(const float* __restrict__ bq, const float* __restrict__ bk,
                   const float* __restrict__ bv)
{
    extern __shared__ __nv_bfloat16 qsm[];
    int mode = blockIdx.z;
    const __nv_bfloat16* A = g_Abf + (size_t)mode*(B_*L_*H_);
    const __nv_bfloat16* W = g_Wbf + mode*(H_*H_);
    const float* bias = mode == 0 ? bq : (mode == 1 ? bk : bv);

    const int m0 = blockIdx.y * 128, n0 = blockIdx.x * 128;
    const int tid = threadIdx.x, lane = tid & 31, w = tid >> 5;
    const int wr = w >> 1, wc = w & 1, g = lane >> 2, qd = lane & 3;

    __nv_bfloat16* Abuf[3]; __nv_bfloat16* Wbuf[3];
    #pragma unroll
    for (int b = 0; b < 3; b++) {
        Abuf[b] = qsm + b*2*128*QKP;
        Wbuf[b] = Abuf[b] + 128*QKP;
    }

    auto cp_chunk = [&](int kc) {
        int b = kc % 3;
        uint32_t as = smem_u32(Abuf[b]);
        uint32_t ws = smem_u32(Wbuf[b]);
        const __nv_bfloat16* Ag = A + (size_t)m0 * H_ + kc*32;
        const __nv_bfloat16* Wg = W + (size_t)n0 * H_ + kc*32;
        #pragma unroll
        for (int t = tid; t < 512; t += 256) {
            int r = t >> 2, c = (t & 3) * 8;
            cp16(as + (r*QKP + c)*2, Ag + (size_t)r * H_ + c);
            cp16(ws + (r*QKP + c)*2, Wg + (size_t)r * H_ + c);
        }
        CP_COMMIT();
    };

    uint32_t qaA[3], wbaA[3];
    #pragma unroll
    for (int b = 0; b < 3; b++) {
        qaA[b]  = smem_u32(Abuf[b] + (wr*32 + (lane & 15))*QKP + ((lane >> 4) & 1)*8);
        wbaA[b] = smem_u32(Wbuf[b] + (wc*64 + ((lane >> 4) & 1)*8 + (lane & 7))*QKP
                           + ((lane >> 3) & 1)*8);
    }

    float acc[2][8][4] = {};

    cp_chunk(0);
    cp_chunk(1);

    for (int kc = 0; kc < 16; kc++) {
        if (kc < 15) asm volatile("cp.async.wait_group 1;" ::: "memory");
        else         asm volatile("cp.async.wait_group 0;" ::: "memory");
        __syncthreads();
        if (kc < 14) cp_chunk(kc + 2);

        int b = kc % 3;
        #pragma unroll
        for (int kk = 0; kk < 2; kk++) {
            uint32_t a0[4], a1[4];
            ldsm_x4(a0, qaA[b] + kk*32);
            ldsm_x4(a1, qaA[b] + 16*QKP*2 + kk*32);
            #pragma unroll
            for (int p = 0; p < 4; p++) {
                uint32_t bb[4];
                ldsm_x4(bb, wbaA[b] + p*(16*QKP*2) + kk*32);
                mma16816(acc[0][2*p+0], a0, bb[0], bb[1]);
                mma16816(acc[0][2*p+1], a0, bb[2], bb[3]);
                mma16816(acc[1][2*p+0], a1, bb[0], bb[1]);
                mma16816(acc[1][2*p+1], a1, bb[2], bb[3]);
            }
        }
    }

    const float qsA = 0.5f * LOG2E;
    #pragma unroll
    for (int mf = 0; mf < 2; mf++) {
        int rg = m0 + wr*32 + mf*16 + g;
        int b = rg >> 11, l = rg & (L_ - 1);
        #pragma unroll
        for (int nf = 0; nf < 8; nf++) {
            int n = n0 + wc*64 + nf*8 + qd*2;
            int h = n >> 6, d = n & 63;
            float b0 = bias[n], b1 = bias[n+1];
            float v00 = acc[mf][nf][0] + b0, v01 = acc[mf][nf][1] + b1;
            float v10 = acc[mf][nf][2] + b0, v11 = acc[mf][nf][3] + b1;
            size_t o0 = ((size_t)(b*NH + h) * L_ + l) * D_ + d;
            size_t o1 = o0 + 8*D_;
            if (mode == 0) {
                *(uint16_t*)(g_Qf8 + o0) = cvt_e4m3x2(v00*qsA, v01*qsA);
                *(uint16_t*)(g_Qf8 + o1) = cvt_e4m3x2(v10*qsA, v11*qsA);
            } else if (mode == 1) {
                *(uint16_t*)(g_Kf8 + o0) = cvt_e4m3x2(v00*0.25f, v01*0.25f);
                *(uint16_t*)(g_Kf8 + o1) = cvt_e4m3x2(v10*0.25f, v11*0.25f);
            } else {
                *(float2*)(g_V + o0) = make_float2(v00, v01);
                *(float2*)(g_V + o1) = make_float2(v10, v11);
            }
        }
    }
}

// ---------------- Kernel 2: e4m3 score pass, 64-row i-tile, 2 CTA/SM ------------
#define PSP 520
#define A_KS0 5120
#define A_KS1 15360
#define A_WS0 25600
#define A_WS1 35840
#define A_PS  46080
#define A_WB  112640
#define A_SD  113664
#define A_RED 113920
#define ATT_SMEM 114944

__global__ __launch_bounds__(256, 2)
void attn_mma_kernel(const float* __restrict__ Wpb)
{
    extern __shared__ char smc[];
    __nv_bfloat16* Psm = (__nv_bfloat16*)(smc + A_PS);
    float* wbn   = (float*)(smc + A_WB);
    float* sdArr = (float*)(smc + A_SD);
    float* red   = (float*)(smc + A_RED);

    const int tid = threadIdx.x;
    const int lane = tid & 31, w = tid >> 5;
    const int wr = w >> 2, wc = w & 3;          // wr 0..1 (32 rows), wc 0..3 (32 cols)
    const int g = lane >> 2, qd = lane & 3;
    const int bh = blockIdx.y, it = blockIdx.x; // it 0..31, i-tile 64 rows
    const int half = blockIdx.z;
    const int js = half * 8;
    const int i0 = it * 64;
    const int dOff = 64 * (it & 1);             // diag col offset within its j-tile
    const int diag_jt = it >> 1;

    const uint32_t qs_s = smem_u32(smc);
    const uint32_t ks_s[2] = { qs_s + A_KS0, qs_s + A_KS1 };
    const uint32_t ws_s[2] = { qs_s + A_WS0, qs_s + A_WS1 };

    // 128-row x 64-byte e4m3 tile, pitch FPP
    auto cp_tile = [&](uint32_t sbase, const uint8_t* gsrc) {
        #pragma unroll
        for (int ch = tid; ch < 512; ch += 256) {
            int r = ch >> 2, c = (ch & 3) * 16;
            cp16(sbase + r*FPP + c, gsrc + r*64 + c);
        }
    };

    const int rbase0 = 128*js + 1984 - 64*it;   // first Wp row needed (>=0)
    const int wb0 = rbase0 & ~127;              // 128-aligned window base

    // ---- prolog: Q(64 rows), K tile js, W blocks wb0 -> ws1, wb0+128 -> ws0
    {
        const uint8_t* gq = g_Qf8 + ((size_t)bh * L_ + i0) * D_;
        int r = tid >> 2, c = (tid & 3) * 16;
        cp16(qs_s + r*FPP + c, gq + r*64 + c);
    }
    cp_tile(ks_s[0], g_Kf8 + ((size_t)bh * L_ + js*128) * D_);
    cp_tile(ws_s[1], g_Wpf8 + (size_t)wb0 * D_);
    cp_tile(ws_s[0], g_Wpf8 + (size_t)(wb0 + 128) * D_);
    CP_COMMIT();
    if (tid < 128) {
        int ia = wb0 + tid;
        int ib = wb0 + 128 + tid;
        wbn[128 + tid] = (ia < 2*L_ - 1) ? Wpb[ia] * LOG2E : 0.f;
        wbn[tid]       = (ib < 2*L_ - 1) ? Wpb[ib] * LOG2E : 0.f;
    }
    asm volatile("cp.async.wait_group 0;" ::: "memory");
    __syncthreads();

    // Q fragments cached for whole kernel
    uint32_t qf[2][2][4];
    {
        uint32_t qa0 = qs_s + (wr*32 + (lane & 15))*FPP + ((lane >> 4) & 1)*16;
        uint32_t qa1 = qa0 + 16*FPP;
        #pragma unroll
        for (int kk = 0; kk < 2; kk++) {
            ldsm_x4(qf[kk][0], qa0 + kk*32);
            ldsm_x4(qf[kk][1], qa1 + kk*32);
        }
    }

    const uint32_t boff = (((lane >> 4) & 1)*8 + (lane & 7))*FPP + ((lane >> 3) & 1)*16;
    const uint32_t bline = wc*32*FPP;

    float accP[2][2][4];
    float accS[2][4][4];
    float rs[4] = {0.f, 0.f, 0.f, 0.f};

    auto pblock_half = [&](uint32_t ws_base, int h) {
        const uint32_t ba = ws_base + bline + boff + h*(16*FPP);
        uint32_t bb[4];
        ldsm_x4(bb, ba);
        mma_f8_z(accP[0][0], qf[0][0], bb[0], bb[1]);
        mma_f8_z(accP[0][1], qf[0][0], bb[2], bb[3]);
        mma_f8_z(accP[1][0], qf[0][1], bb[0], bb[1]);
        mma_f8_z(accP[1][1], qf[0][1], bb[2], bb[3]);
        ldsm_x4(bb, ba + 32);
        mma_f8(accP[0][0], qf[1][0], bb[0], bb[1]);
        mma_f8(accP[0][1], qf[1][0], bb[2], bb[3]);
        mma_f8(accP[1][0], qf[1][1], bb[0], bb[1]);
        mma_f8(accP[1][1], qf[1][1], bb[2], bb[3]);
    };
    auto store_half = [&](const float* wb, int slot, int h) {
        int pb = slot * 128;
        const float ps = 0.015625f;   // 1/64
        #pragma unroll
        for (int mf = 0; mf < 2; mf++) {
            int r0 = wr*32 + mf*16 + g, r1 = r0 + 8;
            #pragma unroll
            for (int nf = 0; nf < 2; nf++) {
                int c = wc*32 + (h*2 + nf)*8 + qd*2;
                float b0 = wb[c], b1 = wb[c+1];
                __nv_bfloat162 v0 = cvt2(accP[mf][nf][0]*ps + b0, accP[mf][nf][1]*ps + b1);
                __nv_bfloat162 v1 = cvt2(accP[mf][nf][2]*ps + b0, accP[mf][nf][3]*ps + b1);
                *(__nv_bfloat162*)&Psm[r0*PSP + pb + c] = v0;
                *(__nv_bfloat162*)&Psm[r1*PSP + pb + c] = v1;
                if (slot == 0) {
                    *(__nv_bfloat162*)&Psm[r0*PSP + 384 + c] = v0;
                    *(__nv_bfloat162*)&Psm[r1*PSP + 384 + c] = v1;
                }
            }
        }
    };
    auto smma = [&](uint32_t ks_base) {
        const uint32_t kb0a = ks_base + bline + boff;
        const uint32_t kb1a = kb0a + 16*FPP;
        uint32_t b0v[4], b1v[4];
        ldsm_x4(b0v, kb0a);
        ldsm_x4(b1v, kb1a);
        mma_f8_z(accS[0][0], qf[0][0], b0v[0], b0v[1]);
        mma_f8_z(accS[0][1], qf[0][0], b0v[2], b0v[3]);
        mma_f8_z(accS[0][2], qf[0][0], b1v[0], b1v[1]);
        mma_f8_z(accS[0][3], qf[0][0], b1v[2], b1v[3]);
        mma_f8_z(accS[1][0], qf[0][1], b0v[0], b0v[1]);
        mma_f8_z(accS[1][1], qf[0][1], b0v[2], b0v[3]);
        mma_f8_z(accS[1][2], qf[0][1], b1v[0], b1v[1]);
        mma_f8_z(accS[1][3], qf[0][1], b1v[2], b1v[3]);
        ldsm_x4(b0v, kb0a + 32);
        ldsm_x4(b1v, kb1a + 32);
        mma_f8(accS[0][0], qf[1][0], b0v[0], b0v[1]);
        mma_f8(accS[0][1], qf[1][0], b0v[2], b0v[3]);
        mma_f8(accS[0][2], qf[1][0], b1v[0], b1v[1]);
        mma_f8(accS[0][3], qf[1][0], b1v[2], b1v[3]);
        mma_f8(accS[1][0], qf[1][1], b0v[0], b0v[1]);
        mma_f8(accS[1][1], qf[1][1], b0v[2], b0v[3]);
        mma_f8(accS[1][2], qf[1][1], b1v[0], b1v[1]);
        mma_f8(accS[1][3], qf[1][1], b1v[2], b1v[3]);
    };
    auto epilogue = [&](int Rbm, bool dt) {
        uint32_t hacc[4] = {0u, 0u, 0u, 0u};
        #pragma unroll
        for (int mf = 0; mf < 2; mf++) {
            int r0 = wr*32 + mf*16 + g, r1 = r0 + 8;
            int m0v = Rbm - r0; if (m0v < 0) m0v += 384;
            int m1v = Rbm - r1; if (m1v < 0) m1v += 384;
            const __nv_bfloat16* base0 = Psm + r0*PSP + m0v;
            const __nv_bfloat16* base1 = Psm + r1*PSP + m1v;
            #pragma unroll
            for (int nf = 0; nf < 4; nf++) {
                int j = wc*32 + nf*8 + qd*2;
                float t00 = accS[mf][nf][0] + __bfloat162float(base0[j]);
                float t01 = accS[mf][nf][1] + __bfloat162float(base0[j+1]);
                float t10 = accS[mf][nf][2] + __bfloat162float(base1[j]);
                float t11 = accS[mf][nf][3] + __bfloat162float(base1[j+1]);
                exp2_acc_f16x2(hacc[mf*2+0], t00, t01);
                exp2_acc_f16x2(hacc[mf*2+1], t10, t11);
                if (dt) {
                    if (j == r0 + dOff)          sdArr[r0] = t00;
                    else if (j + 1 == r0 + dOff) sdArr[r0] = t01;
                    if (j == r1 + dOff)          sdArr[r1] = t10;
                    else if (j + 1 == r1 + dOff) sdArr[r1] = t11;
                }
            }
        }
        #pragma unroll
        for (int k = 0; k < 4; k++) {
            __half2 hv = *reinterpret_cast<__half2*>(&hacc[k]);
            rs[k] += __low2float(hv) + __high2float(hv);
        }
    };

    int sigma = (wb0 >> 7) % 3;
    pblock_half(ws_s[1], 0); store_half(wbn + 128, sigma, 0);
    pblock_half(ws_s[1], 1); store_half(wbn + 128, sigma, 1);

    int Rbm = (128*js - 64*it + 2047) % 384;
    int RbmPrev = Rbm;

    for (int t = 0; t < 8; t++) {
        int jt = js + t;
        int cur = t & 1, nxt = cur ^ 1;
        int s_w = sigma + 1; if (s_w == 3) s_w = 0;

        asm volatile("cp.async.wait_group 0;" ::: "memory");
        __syncthreads();

        if (t < 7) {
            if (tid < 128) {
                int idx = wb0 + (t+2)*128 + tid;
                wbn[nxt*128 + tid] = (idx < 2*L_ - 1) ? Wpb[idx] * LOG2E : 0.f;
            }
            cp_tile(ks_s[nxt], g_Kf8 + ((size_t)bh * L_ + (jt+1)*128) * D_);
            cp_tile(ws_s[nxt], g_Wpf8 + (size_t)(wb0 + (t+2)*128) * D_);
            CP_COMMIT();
        }

        pblock_half(ws_s[cur], 0); store_half(wbn + cur*128, s_w, 0);
        pblock_half(ws_s[cur], 1); store_half(wbn + cur*128, s_w, 1);
        if (t > 0) epilogue(RbmPrev, (jt-1) == diag_jt);
        smma(ks_s[cur]);

        RbmPrev = Rbm;
        Rbm += 128; if (Rbm >= 384) Rbm -= 384;
        sigma = s_w;
    }

    __syncthreads();
    epilogue(RbmPrev, (js + 7) == diag_jt);

    #pragma unroll
    for (int k = 0; k < 4; k++) {
        rs[k] += __shfl_xor_sync(0xffffffffu, rs[k], 1);
        rs[k] += __shfl_xor_sync(0xffffffffu, rs[k], 2);
    }
    if (qd == 0) {
        int base = wc*64 + wr*32 + g;
        red[base]      = rs[0];
        red[base + 8]  = rs[1];
        red[base + 16] = rs[2];
        red[base + 24] = rs[3];
    }
    __syncthreads();
    if (tid < 64) {
        float r = red[tid] + red[64 + tid] + red[128 + tid] + red[192 + tid];
        size_t o = (size_t)bh * L_ + i0 + tid;
        if (half) g_RS1[o] = r; else g_RS0[o] = r;
        if ((it >> 4) == half) g_SD[o] = sdArr[tid];
    }
}

// ---------------- Kernel 3: O projection, smem diag table, fused diag*V ---------
__global__ __launch_bounds__(256, 2)
void gemm_out_bf16(const float* __restrict__ Wo, const float* __restrict__ bo,
                   float* __restrict__ out)
{
    __shared__ __nv_bfloat16 Ab[2][128*KP];
    __shared__ __nv_bfloat16 Wb[2][128*KP];
    __shared__ float dgs[NH*128];

    const int m0 = blockIdx.y * 128, n0 = blockIdx.x * 128;
    const int tid = threadIdx.x, lane = tid & 31, w = tid >> 5;
    const int wr = w >> 1, wc = w & 1, g = lane >> 2, qd = lane & 3;
    const int rr = tid >> 3;
    const int c4 = (tid & 7) * 4;

    const int bq = m0 >> 11, l0 = m0 & (L_ - 1);

    for (int t = tid; t < NH*128; t += 256) {
        int h = t >> 7, r = t & 127;
        size_t row = (size_t)(bq*NH + h) * L_ + l0 + r;
        dgs[t] = fast_exp2(g_SD[row]) * fast_rcp(g_RS0[row] + g_RS1[row]);
    }
    __syncthreads();

    float4 ra[4], rw[4];
    auto ldg_chunk = [&](int kc) {
        int h = kc >> 1;
        const float* Ag = g_V + ((size_t)(bq*NH + h) * L_ + l0) * D_ + (kc & 1)*32;
        const float* Wg = Wo + (size_t)n0 * H_ + kc*32;
        #pragma unroll
        for (int i = 0; i < 4; i++) {
            int r = i*32 + rr;
            ra[i] = *(const float4*)&Ag[(size_t)r * D_ + c4];
            rw[i] = *(const float4*)&Wg[(size_t)r * H_ + c4];
        }
    };
    auto sts_chunk = [&](int buf, int kc) {
        const float* dg = dgs + (kc >> 1)*128;
        #pragma unroll
        for (int i = 0; i < 4; i++) {
            int r = i*32 + rr;
            float d = dg[r];
            __nv_bfloat162* pa = (__nv_bfloat162*)(Ab[buf] + r*KP + c4);
            pa[0] = cvt2(ra[i].x*d, ra[i].y*d);
            pa[1] = cvt2(ra[i].z*d, ra[i].w*d);
            __nv_bfloat162* pw = (__nv_bfloat162*)(Wb[buf] + r*KP + c4);
            pw[0] = cvt2(rw[i].x, rw[i].y);
            pw[1] = cvt2(rw[i].z, rw[i].w);
        }
    };

    uint32_t qaA[2], wbaA[2];
    #pragma unroll
    for (int b = 0; b < 2; b++) {
        qaA[b]  = smem_u32(Ab[b] + (wr*32 + (lane & 15))*KP + ((lane >> 4) & 1)*8);
        wbaA[b] = smem_u32(Wb[b] + (wc*64 + ((lane >> 4) & 1)*8 + (lane & 7))*KP
                           + ((lane >> 3) & 1)*8);
    }

    float acc[2][8][4] = {};

    ldg_chunk(0);
    sts_chunk(0, 0);
    ldg_chunk(1);

    for (int kc = 0; kc < 16; kc++) {
        int cur = kc & 1;
        __syncthreads();
        #pragma unroll
        for (int kk = 0; kk < 2; kk++) {
            uint32_t a0[4], a1[4];
            ldsm_x4(a0, qaA[cur] + kk*32);
            ldsm_x4(a1, qaA[cur] + 16*KP*2 + kk*32);
            #pragma unroll
            for (int p = 0; p < 4; p++) {
                uint32_t bb[4];
                ldsm_x4(bb, wbaA[cur] + p*(16*KP*2) + kk*32);
                mma16816(acc[0][2*p+0], a0, bb[0], bb[1]);
                mma16816(acc[0][2*p+1], a0, bb[2], bb[3]);
                mma16816(acc[1][2*p+0], a1, bb[0], bb[1]);
                mma16816(acc[1][2*p+1], a1, bb[2], bb[3]);
            }
        }
        if (kc < 15) {
            sts_chunk(cur ^ 1, kc + 1);
            if (kc < 14) ldg_chunk(kc + 2);
        }
    }

    #pragma unroll
    for (int mf = 0; mf < 2; mf++) {
        int rg = m0 + wr*32 + mf*16 + g;
        #pragma unroll
        for (int nf = 0; nf < 8; nf++) {
            int n = n0 + wc*64 + nf*8 + qd*2;
            float b0 = bo[n], b1 = bo[n+1];
            *(float2*)(out + (size_t)rg * H_ + n) =
                make_float2(acc[mf][nf][0] + b0, acc[mf][nf][1] + b1);
            *(float2*)(out + (size_t)(rg + 8) * H_ + n) =
                make_float2(acc[mf][nf][2] + b0, acc[mf][nf][3] + b1);
        }
    }
}

// ---------------- launch --------------------------------------------------------
extern "C" void kernel_launch(void* const* d_in, const int* in_sizes, int n_in,
                              void* d_out, int out_size)
{
    const float* q_in = (const float*)d_in[0];
    const float* k_in = (const float*)d_in[1];
    const float* v_in = (const float*)d_in[2];
    const float* Wq_w = (const float*)d_in[3];
    const float* Wq_b = (const float*)d_in[4];
    const float* Wk_w = (const float*)d_in[5];
    const float* Wk_b = (const float*)d_in[6];
    const float* Wv_w = (const float*)d_in[7];
    const float* Wv_b = (const float*)d_in[8];
    const float* Wo_w = (const float*)d_in[9];
    const float* Wo_b = (const float*)d_in[10];
    const float* Wp_w = (const float*)d_in[11];
    const float* Wp_b = (const float*)d_in[12];

    cudaFuncSetAttribute(attn_mma_kernel,
                         cudaFuncAttributeMaxDynamicSharedMemorySize, ATT_SMEM);
    cudaFuncSetAttribute(gemm_qkv_bf16,
                         cudaFuncAttributeMaxDynamicSharedMemorySize, QKV_SMEM);

    convert_kernel<<<13312, 256>>>(q_in, k_in, v_in, Wq_w, Wk_w, Wv_w, Wp_w);

    gemm_qkv_bf16<<<dim3(H_/128, (B_*L_)/128, 3), 256, QKV_SMEM>>>(Wq_b, Wk_b, Wv_b);

    attn_mma_kernel<<<dim3(32, B_*NH, 2), 256, ATT_SMEM>>>(Wp_b);

    gemm_out_bf16<<<dim3(H_/128, (B_*L_)/128), 256>>>(Wo_w, Wo_b, (float*)d_out);
}